// round 11
// baseline (speedup 1.0000x reference)
#include <cuda_runtime.h>

// Problem constants (fixed by setup_inputs): B=4, N=M=8192, D=3
constexpr int Bn   = 4;
constexpr int Np   = 8192;
constexpr int NPTS = 2 * Bn * Np;   // 65536 points total (both clouds)
constexpr int GD   = 48;            // grid cells per axis
constexpr int NC   = GD * GD * GD;  // 110592 cells per (cloud,batch)
constexpr int NSEG = 2 * Bn;        // 8 segments: cloud (src/tgt) x batch
constexpr float HLO  = -6.0f;       // grid domain [-6, 6] (normal data |x| < ~4.5)
constexpr float H    = 0.25f;       // cell size
constexpr float INVH = 4.0f;

// Scratch (static __device__, no allocs). Everything here is rewritten each
// call; g_cnt is zeroed by a kernel first (atomics accumulate into it).
__device__ int    g_cnt  [NSEG * NC];
__device__ int    g_start[NSEG * NC];
__device__ int    g_cur  [NSEG * NC];
__device__ float4 g_pts  [NSEG * Np];   // cell-sorted points, .w = original idx bits
__device__ float  g_mind [NPTS];        // min d2 per (dir, batch, ORIGINAL idx)

__device__ __forceinline__ int cellof(float v) {
    int c = __float2int_rd((v - HLO) * INVH);
    return min(max(c, 0), GD - 1);
}

// ---- build stage ----

__global__ void zero_cnt() {
    int i = blockIdx.x * blockDim.x + threadIdx.x;   // 864*1024 == NSEG*NC
    g_cnt[i] = 0;
}

__global__ void count_pts(const float* __restrict__ src, const float* __restrict__ tgt) {
    int t  = blockIdx.x * blockDim.x + threadIdx.x;  // 65536
    int c  = t >> 15;            // cloud: 0=src, 1=tgt
    int rr = t & 32767;          // b*8192 + i
    const float* p = (c ? tgt : src) + (size_t)rr * 3;
    int ci = (cellof(p[2]) * GD + cellof(p[1])) * GD + cellof(p[0]);
    int seg = c * Bn + (rr >> 13);
    atomicAdd(&g_cnt[seg * NC + ci], 1);
}

// One block per segment: serial chunk sums + Hillis-Steele scan of 1024 partials.
__global__ void scan_cells() {
    __shared__ int sh[1024];
    const int tid  = threadIdx.x;
    const int base = blockIdx.x * NC + tid * (NC / 1024);  // NC/1024 = 108
    int s = 0;
    for (int k = 0; k < NC / 1024; k++) s += g_cnt[base + k];
    sh[tid] = s;
    __syncthreads();
    int v = s;
    for (int off = 1; off < 1024; off <<= 1) {
        int u = (tid >= off) ? sh[tid - off] : 0;
        __syncthreads();
        v += u;
        sh[tid] = v;
        __syncthreads();
    }
    int run = v - s;  // exclusive prefix of this thread's chunk
    for (int k = 0; k < NC / 1024; k++) {
        int c = g_cnt[base + k];
        g_start[base + k] = run;
        g_cur[base + k]   = run;
        run += c;
    }
}

__global__ void scatter_pts(const float* __restrict__ src, const float* __restrict__ tgt) {
    int t  = blockIdx.x * blockDim.x + threadIdx.x;
    int c  = t >> 15;
    int rr = t & 32767;
    const float* p = (c ? tgt : src) + (size_t)rr * 3;
    float x = p[0], y = p[1], z = p[2];
    int ci  = (cellof(z) * GD + cellof(y)) * GD + cellof(x);
    int seg = c * Bn + (rr >> 13);
    int slot = atomicAdd(&g_cur[seg * NC + ci], 1);  // order nondeterministic:
    // harmless — min over the cell's point SET is order-invariant, and results
    // are written back to the ORIGINAL index carried in .w.
    g_pts[seg * Np + slot] = make_float4(x, y, z, __int_as_float(rr & 8191));
}

// ---- exact grid-pruned NN (both directions) ----

__global__ void __launch_bounds__(256)
nn_kernel() {
    int t  = blockIdx.x * blockDim.x + threadIdx.x;  // 65536 queries
    int d  = t >> 15;           // direction: 0 = src->tgt, 1 = tgt->src
    int rr = t & 32767;
    int b  = rr >> 13;
    int k  = rr & 8191;
    const int qseg = d * Bn + b;        // query cloud (sorted -> warp-coherent)
    const int dseg = (1 - d) * Bn + b;  // database cloud
    float4 q = g_pts[qseg * Np + k];

    const int cx = cellof(q.x), cy = cellof(q.y), cz = cellof(q.z);
    const int cbase = dseg * NC;
    const int pbase = dseg * Np;

    float best = 3.4e38f;
    for (int r = 0; r < GD; r++) {
        if (r > 0) {
            // Unexplored cells (Chebyshev >= r) are >= (r-1)*H away. Exact bound.
            float br = (float)(r - 1) * H;
            if (best <= br * br) break;
        }
        int zlo = max(cz - r, 0), zhi = min(cz + r, GD - 1);
        int ylo = max(cy - r, 0), yhi = min(cy + r, GD - 1);
        int xlo = max(cx - r, 0), xhi = min(cx + r, GD - 1);
        for (int z = zlo; z <= zhi; z++) {
            bool zf = (z == cz - r) || (z == cz + r);
            for (int y = ylo; y <= yhi; y++) {
                bool face = zf || (y == cy - r) || (y == cy + r);
                // on a face: full x range; otherwise only x = cx +/- r
                int xa = face ? xlo : (cx - r);
                int xb = face ? xhi : (cx + r);
                int xs = face ? 1 : (2 * r > 0 ? 2 * r : 1);
                for (int x = xa; x <= xb; x += xs) {
                    if (x < 0 || x >= GD) continue;
                    int ci = cbase + (z * GD + y) * GD + x;
                    int st = g_start[ci];
                    int cn = g_cnt[ci];
                    for (int u = 0; u < cn; u++) {
                        float4 tp = g_pts[pbase + st + u];
                        float dx = q.x - tp.x;
                        float dy = q.y - tp.y;
                        float dz = q.z - tp.z;
                        float d2 = fmaf(dx, dx, fmaf(dy, dy, dz * dz));
                        best = fminf(best, d2);
                    }
                }
            }
        }
    }
    int orig = __float_as_int(q.w);
    g_mind[d * (Bn * Np) + b * Np + orig] = best;  // original-index slot
}

// ---- deterministic fixed-order sum ----

__global__ void final_sum(float* out) {
    __shared__ float sh[1024];
    int tid = threadIdx.x;
    float s = 0.0f;
    for (int i = tid; i < NPTS; i += 1024) s += g_mind[i];  // fixed order
    sh[tid] = s;
    __syncthreads();
#pragma unroll
    for (int st = 512; st > 0; st >>= 1) {
        if (tid < st) sh[tid] += sh[tid + st];
        __syncthreads();
    }
    if (tid == 0)
        out[0] = sh[0] / (float)(Bn * Np);  // (sum_fwd + sum_bwd) / (B*G)
}

extern "C" void kernel_launch(void* const* d_in, const int* in_sizes, int n_in,
                              void* d_out, int out_size) {
    const float* src = (const float*)d_in[0];  // (4, 8192, 3) fp32
    const float* tgt = (const float*)d_in[1];  // (4, 8192, 3) fp32
    float* out = (float*)d_out;

    zero_cnt<<<(NSEG * NC) / 1024, 1024>>>();
    count_pts<<<NPTS / 256, 256>>>(src, tgt);
    scan_cells<<<NSEG, 1024>>>();
    scatter_pts<<<NPTS / 256, 256>>>(src, tgt);
    nn_kernel<<<NPTS / 256, 256>>>();
    final_sum<<<1, 1024>>>(out);
}

// round 12
// speedup vs baseline: 6.1260x; 6.1260x over previous
#include <cuda_runtime.h>

// Problem constants (fixed by setup_inputs): B=4, N=M=8192, D=3
constexpr int Bn   = 4;
constexpr int Np   = 8192;
constexpr int NPTS = 2 * Bn * Np;   // 65536 queries total (both directions)
constexpr int GD   = 24;            // grid cells per axis
constexpr int NC   = GD * GD * GD;  // 13824 cells per (cloud,batch)
constexpr int NSEG = 2 * Bn;        // 8 segments: cloud (src/tgt) x batch
constexpr float HLO  = -6.0f;       // grid domain [-6, 6]
constexpr float H    = 0.5f;        // cell size
constexpr float INVH = 2.0f;
constexpr float BOUND2 = H * H;     // 3^3 neighborhood exactness bound

// Scratch (static __device__, no allocs). All state rewritten every call.
__device__ int    g_cnt [NSEG * NC];
__device__ int2   g_cell[NSEG * NC];   // (start, count)
__device__ int    g_cur [NSEG * NC];
__device__ float4 g_pts [NSEG * Np];   // cell-sorted points, .w = original idx bits
__device__ float  g_mind[NPTS];        // min d2 per (dir, batch, ORIGINAL idx)
__device__ int    g_fq  [NPTS];        // unresolved query tokens
__device__ int    g_fcnt;

__device__ __forceinline__ int cellof(float v) {
    int c = __float2int_rd((v - HLO) * INVH);
    return min(max(c, 0), GD - 1);
}
__device__ __forceinline__ unsigned redux_min(unsigned v) {
    unsigned d;
    asm("redux.sync.min.u32 %0, %1, 0xffffffff;" : "=r"(d) : "r"(v));
    return d;
}

// ---- build stage ----

__global__ void zero_cnt() {
    int i = blockIdx.x * blockDim.x + threadIdx.x;   // 108*1024 == NSEG*NC
    g_cnt[i] = 0;
    if (i == 0) g_fcnt = 0;
}

__global__ void count_pts(const float* __restrict__ src, const float* __restrict__ tgt) {
    int t  = blockIdx.x * blockDim.x + threadIdx.x;  // 65536
    int c  = t >> 15;            // cloud: 0=src, 1=tgt
    int rr = t & 32767;          // b*8192 + i
    const float* p = (c ? tgt : src) + (size_t)rr * 3;
    int ci = (cellof(p[2]) * GD + cellof(p[1])) * GD + cellof(p[0]);
    int seg = c * Bn + (rr >> 13);
    atomicAdd(&g_cnt[seg * NC + ci], 1);
}

// One block per segment: serial chunk sums + Hillis-Steele scan of 1024 partials.
__global__ void scan_cells() {
    __shared__ int sh[1024];
    constexpr int CH = (NC + 1023) / 1024;  // 14
    const int tid  = threadIdx.x;
    const int base = blockIdx.x * NC;
    int s = 0;
    for (int k = 0; k < CH; k++) {
        int idx = tid * CH + k;
        if (idx < NC) s += g_cnt[base + idx];
    }
    sh[tid] = s;
    __syncthreads();
    int v = s;
    for (int off = 1; off < 1024; off <<= 1) {
        int u = (tid >= off) ? sh[tid - off] : 0;
        __syncthreads();
        v += u;
        sh[tid] = v;
        __syncthreads();
    }
    int run = v - s;  // exclusive prefix of this thread's chunk
    for (int k = 0; k < CH; k++) {
        int idx = tid * CH + k;
        if (idx < NC) {
            int c = g_cnt[base + idx];
            g_cell[base + idx] = make_int2(run, c);
            g_cur[base + idx]  = run;
            run += c;
        }
    }
}

__global__ void scatter_pts(const float* __restrict__ src, const float* __restrict__ tgt) {
    int t  = blockIdx.x * blockDim.x + threadIdx.x;
    int c  = t >> 15;
    int rr = t & 32767;
    const float* p = (c ? tgt : src) + (size_t)rr * 3;
    float x = p[0], y = p[1], z = p[2];
    int ci  = (cellof(z) * GD + cellof(y)) * GD + cellof(x);
    int seg = c * Bn + (rr >> 13);
    int slot = atomicAdd(&g_cur[seg * NC + ci], 1);  // order-nondet, set-min invariant
    g_pts[seg * Np + slot] = make_float4(x, y, z, __int_as_float(rr & 8191));
}

// ---- phase 1: uniform 3^3-neighborhood search ----

__global__ void __launch_bounds__(256)
nn_local() {
    int t  = blockIdx.x * blockDim.x + threadIdx.x;  // 65536 queries
    int d  = t >> 15;           // direction: 0 = src->tgt, 1 = tgt->src
    int rr = t & 32767;
    int b  = rr >> 13;
    int k  = rr & 8191;
    const int qseg = d * Bn + b;        // query cloud (cell-sorted -> coherent warps)
    const int dseg = (1 - d) * Bn + b;  // database cloud
    float4 q = g_pts[qseg * Np + k];

    const int cx = cellof(q.x), cy = cellof(q.y), cz = cellof(q.z);
    const int cbase = dseg * NC;
    const int pbase = dseg * Np;

    float best = 3.4e38f;
#pragma unroll
    for (int dz = -1; dz <= 1; dz++) {
        int z = cz + dz;
        if (z < 0 || z >= GD) continue;
#pragma unroll
        for (int dy = -1; dy <= 1; dy++) {
            int y = cy + dy;
            if (y < 0 || y >= GD) continue;
            int rowc = cbase + (z * GD + y) * GD + cx;
#pragma unroll
            for (int dx = -1; dx <= 1; dx++) {
                int x = cx + dx;
                if (x < 0 || x >= GD) continue;
                int2 sc = g_cell[rowc + dx];
                for (int u = 0; u < sc.y; u++) {
                    float4 tp = g_pts[pbase + sc.x + u];
                    float ddx = q.x - tp.x;
                    float ddy = q.y - tp.y;
                    float ddz = q.z - tp.z;
                    float d2 = fmaf(ddx, ddx, fmaf(ddy, ddy, ddz * ddz));
                    best = fminf(best, d2);
                }
            }
        }
    }
    // Any point outside the 3^3 neighborhood is > H away -> exact iff best <= H^2.
    if (best <= BOUND2) {
        int orig = __float_as_int(q.w);
        g_mind[d * (Bn * Np) + b * Np + orig] = best;
    } else {
        g_fq[atomicAdd(&g_fcnt, 1)] = t;  // defer to uniform brute-force pass
    }
}

// ---- phase 2: one warp per unresolved query, full coalesced scan ----

__global__ void __launch_bounds__(256)
nn_far() {
    const int lane = threadIdx.x & 31;
    const int wid  = (blockIdx.x * blockDim.x + threadIdx.x) >> 5;  // 2048 warps
    const int nf   = g_fcnt;
    for (int fi = wid; fi < nf; fi += 2048) {
        int t  = g_fq[fi];
        int d  = t >> 15;
        int rr = t & 32767;
        int b  = rr >> 13;
        int k  = rr & 8191;
        float4 q = g_pts[(d * Bn + b) * Np + k];
        const int pbase = ((1 - d) * Bn + b) * Np;

        float best = 3.4e38f;
        for (int i = lane; i < Np; i += 32) {   // coalesced LDG.128 scan
            float4 tp = g_pts[pbase + i];
            float ddx = q.x - tp.x;
            float ddy = q.y - tp.y;
            float ddz = q.z - tp.z;
            float d2 = fmaf(ddx, ddx, fmaf(ddy, ddy, ddz * ddz));
            best = fminf(best, d2);
        }
        // d2 >= 0 in difference form -> raw bits order as uint
        unsigned m = redux_min(__float_as_uint(best));
        if (lane == 0) {
            int orig = __float_as_int(q.w);
            g_mind[d * (Bn * Np) + b * Np + orig] = __uint_as_float(m);
        }
    }
}

// ---- deterministic fixed-order sum ----

__global__ void final_sum(float* out) {
    __shared__ float sh[1024];
    int tid = threadIdx.x;
    float s = 0.0f;
    for (int i = tid; i < NPTS; i += 1024) s += g_mind[i];  // fixed order
    sh[tid] = s;
    __syncthreads();
#pragma unroll
    for (int st = 512; st > 0; st >>= 1) {
        if (tid < st) sh[tid] += sh[tid + st];
        __syncthreads();
    }
    if (tid == 0)
        out[0] = sh[0] / (float)(Bn * Np);  // (sum_fwd + sum_bwd) / (B*G)
}

extern "C" void kernel_launch(void* const* d_in, const int* in_sizes, int n_in,
                              void* d_out, int out_size) {
    const float* src = (const float*)d_in[0];  // (4, 8192, 3) fp32
    const float* tgt = (const float*)d_in[1];  // (4, 8192, 3) fp32
    float* out = (float*)d_out;

    zero_cnt<<<(NSEG * NC) / 1024, 1024>>>();
    count_pts<<<NPTS / 256, 256>>>(src, tgt);
    scan_cells<<<NSEG, 1024>>>();
    scatter_pts<<<NPTS / 256, 256>>>(src, tgt);
    nn_local<<<NPTS / 256, 256>>>();
    nn_far<<<256, 256>>>();
    final_sum<<<1, 1024>>>(out);
}

// round 13
// speedup vs baseline: 6.3686x; 1.0396x over previous
#include <cuda_runtime.h>

// Problem constants (fixed by setup_inputs): B=4, N=M=8192, D=3
constexpr int Bn   = 4;
constexpr int Np   = 8192;
constexpr int NPTS = 2 * Bn * Np;   // 65536 queries total (both directions)
constexpr int GD   = 24;            // grid cells per axis
constexpr int NC   = GD * GD * GD;  // 13824 cells per (cloud,batch)
constexpr int NSEG = 2 * Bn;        // 8 segments: cloud (src/tgt) x batch
constexpr float HLO  = -6.0f;       // grid domain [-6, 6]
constexpr float H    = 0.5f;        // cell size
constexpr float INVH = 2.0f;
constexpr float BOUND2 = H * H;     // 3^3 neighborhood exactness bound

// Scratch (static __device__, no allocs). All state rewritten every call.
__device__ int    g_cnt [NSEG * NC];
__device__ int2   g_cell[NSEG * NC];   // (start, count)
__device__ int    g_cur [NSEG * NC];
__device__ float4 g_pts [NSEG * Np];   // cell-sorted points, .w = original idx bits
__device__ float  g_mind[NPTS];        // min d2 per (dir, batch, ORIGINAL idx)
__device__ int    g_fq  [NPTS];        // unresolved query tokens
__device__ int    g_fcnt;

__device__ __forceinline__ int cellof(float v) {
    int c = __float2int_rd((v - HLO) * INVH);
    return min(max(c, 0), GD - 1);
}
__device__ __forceinline__ unsigned redux_min(unsigned v) {
    unsigned d;
    asm("redux.sync.min.u32 %0, %1, 0xffffffff;" : "=r"(d) : "r"(v));
    return d;
}

// ---- build stage ----

__global__ void zero_cnt() {
    int i = blockIdx.x * blockDim.x + threadIdx.x;   // 108*1024 == NSEG*NC
    g_cnt[i] = 0;
    if (i == 0) g_fcnt = 0;
}

__global__ void count_pts(const float* __restrict__ src, const float* __restrict__ tgt) {
    int t  = blockIdx.x * blockDim.x + threadIdx.x;  // 65536
    int c  = t >> 15;            // cloud: 0=src, 1=tgt
    int rr = t & 32767;          // b*8192 + i
    const float* p = (c ? tgt : src) + (size_t)rr * 3;
    int ci = (cellof(p[2]) * GD + cellof(p[1])) * GD + cellof(p[0]);
    int seg = c * Bn + (rr >> 13);
    atomicAdd(&g_cnt[seg * NC + ci], 1);
}

// One block per segment: serial chunk sums + Hillis-Steele scan of 1024 partials.
__global__ void scan_cells() {
    __shared__ int sh[1024];
    constexpr int CH = (NC + 1023) / 1024;  // 14
    const int tid  = threadIdx.x;
    const int base = blockIdx.x * NC;
    int s = 0;
    for (int k = 0; k < CH; k++) {
        int idx = tid * CH + k;
        if (idx < NC) s += g_cnt[base + idx];
    }
    sh[tid] = s;
    __syncthreads();
    int v = s;
    for (int off = 1; off < 1024; off <<= 1) {
        int u = (tid >= off) ? sh[tid - off] : 0;
        __syncthreads();
        v += u;
        sh[tid] = v;
        __syncthreads();
    }
    int run = v - s;  // exclusive prefix of this thread's chunk
    for (int k = 0; k < CH; k++) {
        int idx = tid * CH + k;
        if (idx < NC) {
            int c = g_cnt[base + idx];
            g_cell[base + idx] = make_int2(run, c);
            g_cur[base + idx]  = run;
            run += c;
        }
    }
}

__global__ void scatter_pts(const float* __restrict__ src, const float* __restrict__ tgt) {
    int t  = blockIdx.x * blockDim.x + threadIdx.x;
    int c  = t >> 15;
    int rr = t & 32767;
    const float* p = (c ? tgt : src) + (size_t)rr * 3;
    float x = p[0], y = p[1], z = p[2];
    int ci  = (cellof(z) * GD + cellof(y)) * GD + cellof(x);
    int seg = c * Bn + (rr >> 13);
    int slot = atomicAdd(&g_cur[seg * NC + ci], 1);  // order-nondet, set-min invariant
    g_pts[seg * Np + slot] = make_float4(x, y, z, __int_as_float(rr & 8191));
}

// ---- phase 1: uniform 3^3-neighborhood search ----
// Work balance: warp W handles the 32 consecutive sorted queries of window
// (W*613) & 2047 -- bijective scramble spreads dense (Gaussian-center) windows
// across all blocks/SMs while keeping within-warp spatial coherence.

__global__ void __launch_bounds__(256)
nn_local() {
    int gt   = blockIdx.x * blockDim.x + threadIdx.x;
    int W    = gt >> 5;
    int lane = gt & 31;
    int t    = (((W * 613) & 2047) << 5) | lane;   // scrambled query id

    int d  = t >> 15;           // direction: 0 = src->tgt, 1 = tgt->src
    int rr = t & 32767;
    int b  = rr >> 13;
    int k  = rr & 8191;
    const int qseg = d * Bn + b;
    const int dseg = (1 - d) * Bn + b;
    float4 q = g_pts[qseg * Np + k];  // 32 consecutive -> coalesced

    const int cx = cellof(q.x), cy = cellof(q.y), cz = cellof(q.z);
    const int cbase = dseg * NC;
    const int pbase = dseg * Np;
    const int xlo = max(cx - 1, 0), xhi = min(cx + 1, GD - 1);

    float best = 3.4e38f;
#pragma unroll
    for (int dz = -1; dz <= 1; dz++) {
        int z = cz + dz;
        if ((unsigned)z >= (unsigned)GD) continue;
#pragma unroll
        for (int dy = -1; dy <= 1; dy++) {
            int y = cy + dy;
            if ((unsigned)y >= (unsigned)GD) continue;
            int rowb = cbase + (z * GD + y) * GD;
            // Cells xlo..xhi are contiguous in cell index -> their points are
            // one contiguous g_pts range (counting sort). One scan per row.
            int2 c0 = g_cell[rowb + xlo];
            int2 c1 = g_cell[rowb + xhi];
            int e = c1.x + c1.y;
            for (int u = c0.x; u < e; u++) {
                float4 tp = g_pts[pbase + u];
                float ddx = q.x - tp.x;
                float ddy = q.y - tp.y;
                float ddz = q.z - tp.z;
                float d2 = fmaf(ddx, ddx, fmaf(ddy, ddy, ddz * ddz));
                best = fminf(best, d2);
            }
        }
    }
    // Any point outside the 3^3 neighborhood is > H away -> exact iff best <= H^2.
    if (best <= BOUND2) {
        int orig = __float_as_int(q.w);
        g_mind[d * (Bn * Np) + b * Np + orig] = best;
    } else {
        g_fq[atomicAdd(&g_fcnt, 1)] = t;  // defer to uniform brute-force pass
    }
}

// ---- phase 2: one warp per unresolved query, full coalesced scan ----

__global__ void __launch_bounds__(256)
nn_far() {
    const int lane = threadIdx.x & 31;
    const int wid  = (blockIdx.x * blockDim.x + threadIdx.x) >> 5;  // 2048 warps
    const int nf   = g_fcnt;
    for (int fi = wid; fi < nf; fi += 2048) {
        int t  = g_fq[fi];
        int d  = t >> 15;
        int rr = t & 32767;
        int b  = rr >> 13;
        int k  = rr & 8191;
        float4 q = g_pts[(d * Bn + b) * Np + k];
        const int pbase = ((1 - d) * Bn + b) * Np;

        float best = 3.4e38f;
        for (int i = lane; i < Np; i += 32) {   // coalesced LDG.128 scan
            float4 tp = g_pts[pbase + i];
            float ddx = q.x - tp.x;
            float ddy = q.y - tp.y;
            float ddz = q.z - tp.z;
            float d2 = fmaf(ddx, ddx, fmaf(ddy, ddy, ddz * ddz));
            best = fminf(best, d2);
        }
        // d2 >= 0 in difference form -> raw bits order as uint
        unsigned m = redux_min(__float_as_uint(best));
        if (lane == 0) {
            int orig = __float_as_int(q.w);
            g_mind[d * (Bn * Np) + b * Np + orig] = __uint_as_float(m);
        }
    }
}

// ---- deterministic fixed-order sum ----

__global__ void final_sum(float* out) {
    __shared__ float sh[1024];
    int tid = threadIdx.x;
    float s = 0.0f;
    for (int i = tid; i < NPTS; i += 1024) s += g_mind[i];  // fixed order
    sh[tid] = s;
    __syncthreads();
#pragma unroll
    for (int st = 512; st > 0; st >>= 1) {
        if (tid < st) sh[tid] += sh[tid + st];
        __syncthreads();
    }
    if (tid == 0)
        out[0] = sh[0] / (float)(Bn * Np);  // (sum_fwd + sum_bwd) / (B*G)
}

extern "C" void kernel_launch(void* const* d_in, const int* in_sizes, int n_in,
                              void* d_out, int out_size) {
    const float* src = (const float*)d_in[0];  // (4, 8192, 3) fp32
    const float* tgt = (const float*)d_in[1];  // (4, 8192, 3) fp32
    float* out = (float*)d_out;

    zero_cnt<<<(NSEG * NC) / 1024, 1024>>>();
    count_pts<<<NPTS / 256, 256>>>(src, tgt);
    scan_cells<<<NSEG, 1024>>>();
    scatter_pts<<<NPTS / 256, 256>>>(src, tgt);
    nn_local<<<NPTS / 256, 256>>>();
    nn_far<<<256, 256>>>();
    final_sum<<<1, 1024>>>(out);
}

// round 14
// speedup vs baseline: 6.6886x; 1.0503x over previous
#include <cuda_runtime.h>

// Problem constants (fixed by setup_inputs): B=4, N=M=8192, D=3
constexpr int Bn   = 4;
constexpr int Np   = 8192;
constexpr int NPTS = 2 * Bn * Np;   // 65536 queries total (both directions)
constexpr int GD   = 24;            // grid cells per axis
constexpr int NC   = GD * GD * GD;  // 13824 cells per (cloud,batch)
constexpr int NSEG = 2 * Bn;        // 8 segments: cloud (src/tgt) x batch
constexpr float HLO  = -6.0f;       // grid domain [-6, 6]
constexpr float H    = 0.5f;        // cell size
constexpr float INVH = 2.0f;
constexpr float BOUND2 = H * H;     // 3^3 neighborhood exactness bound

// Scratch (static __device__, no allocs). All state rewritten every call.
__device__ int    g_cnt [NSEG * NC];
__device__ int2   g_cell[NSEG * NC];   // (start, count)
__device__ int    g_cur [NSEG * NC];
__device__ float4 g_pts [NSEG * Np];   // cell-sorted points, .w = original idx bits
__device__ float  g_mind[NPTS];        // min d2 per (dir, batch, ORIGINAL idx)
__device__ int    g_fq  [NPTS];        // unresolved query tokens
__device__ int    g_fcnt;

__device__ __forceinline__ int cellof(float v) {
    int c = __float2int_rd((v - HLO) * INVH);
    return min(max(c, 0), GD - 1);
}
__device__ __forceinline__ unsigned redux_min(unsigned v) {
    unsigned d;
    asm("redux.sync.min.u32 %0, %1, 0xffffffff;" : "=r"(d) : "r"(v));
    return d;
}
__device__ __forceinline__ int redux_min_s(int v) {
    int d; asm("redux.sync.min.s32 %0, %1, 0xffffffff;" : "=r"(d) : "r"(v));
    return d;
}
__device__ __forceinline__ int redux_max_s(int v) {
    int d; asm("redux.sync.max.s32 %0, %1, 0xffffffff;" : "=r"(d) : "r"(v));
    return d;
}

// ---- build stage ----

__global__ void zero_cnt() {
    int i = blockIdx.x * blockDim.x + threadIdx.x;   // 108*1024 == NSEG*NC
    g_cnt[i] = 0;
    if (i == 0) g_fcnt = 0;
}

__global__ void count_pts(const float* __restrict__ src, const float* __restrict__ tgt) {
    int t  = blockIdx.x * blockDim.x + threadIdx.x;  // 65536
    int c  = t >> 15;            // cloud: 0=src, 1=tgt
    int rr = t & 32767;          // b*8192 + i
    const float* p = (c ? tgt : src) + (size_t)rr * 3;
    int ci = (cellof(p[2]) * GD + cellof(p[1])) * GD + cellof(p[0]);
    int seg = c * Bn + (rr >> 13);
    atomicAdd(&g_cnt[seg * NC + ci], 1);
}

// One block per segment: serial chunk sums + Hillis-Steele scan of 1024 partials.
__global__ void scan_cells() {
    __shared__ int sh[1024];
    constexpr int CH = (NC + 1023) / 1024;  // 14
    const int tid  = threadIdx.x;
    const int base = blockIdx.x * NC;
    int s = 0;
    for (int k = 0; k < CH; k++) {
        int idx = tid * CH + k;
        if (idx < NC) s += g_cnt[base + idx];
    }
    sh[tid] = s;
    __syncthreads();
    int v = s;
    for (int off = 1; off < 1024; off <<= 1) {
        int u = (tid >= off) ? sh[tid - off] : 0;
        __syncthreads();
        v += u;
        sh[tid] = v;
        __syncthreads();
    }
    int run = v - s;  // exclusive prefix of this thread's chunk
    for (int k = 0; k < CH; k++) {
        int idx = tid * CH + k;
        if (idx < NC) {
            int c = g_cnt[base + idx];
            g_cell[base + idx] = make_int2(run, c);
            g_cur[base + idx]  = run;
            run += c;
        }
    }
}

__global__ void scatter_pts(const float* __restrict__ src, const float* __restrict__ tgt) {
    int t  = blockIdx.x * blockDim.x + threadIdx.x;
    int c  = t >> 15;
    int rr = t & 32767;
    const float* p = (c ? tgt : src) + (size_t)rr * 3;
    float x = p[0], y = p[1], z = p[2];
    int ci  = (cellof(z) * GD + cellof(y)) * GD + cellof(x);
    int seg = c * Bn + (rr >> 13);
    int slot = atomicAdd(&g_cur[seg * NC + ci], 1);  // order-nondet, set-min invariant
    g_pts[seg * Np + slot] = make_float4(x, y, z, __int_as_float(rr & 8191));
}

// ---- phase 1: warp-cooperative 3^3-neighborhood search ----
// Warp W handles 32 consecutive sorted queries of window (W*613)&2047 (balance
// scramble). The warp scans the UNION of its lanes' neighborhoods cooperatively:
// coalesced 32-candidate chunks staged in shared, broadcast-read by all lanes.

__global__ void __launch_bounds__(256)
nn_local() {
    __shared__ float4 buf[8][32];

    int gt   = blockIdx.x * blockDim.x + threadIdx.x;
    int W    = gt >> 5;
    int lane = gt & 31;
    int wloc = (threadIdx.x) >> 5;
    int t    = (((W * 613) & 2047) << 5) | lane;   // scrambled query id

    int d  = t >> 15;           // direction: 0 = src->tgt, 1 = tgt->src
    int rr = t & 32767;
    int b  = rr >> 13;
    int k  = rr & 8191;
    const int qseg = d * Bn + b;
    const int dseg = (1 - d) * Bn + b;
    float4 q = g_pts[qseg * Np + k];  // 32 consecutive -> coalesced

    const int cx = cellof(q.x), cy = cellof(q.y), cz = cellof(q.z);
    const int cbase = dseg * NC;
    const int pbase = dseg * Np;

    const int mzlo = max(cz - 1, 0), mzhi = min(cz + 1, GD - 1);
    const int mylo = max(cy - 1, 0), myhi = min(cy + 1, GD - 1);
    const int mxlo = max(cx - 1, 0), mxhi = min(cx + 1, GD - 1);

    // Warp-union bounds (cover every lane's own 3^3 neighborhood)
    const int zlo = redux_min_s(mzlo), zhi = redux_max_s(mzhi);
    const int ylo = redux_min_s(mylo), yhi = redux_max_s(myhi);
    const int xlo = redux_min_s(mxlo), xhi = redux_max_s(mxhi);

    float best = 3.4e38f;

    if ((zhi - zlo <= 3) && (yhi - ylo <= 3)) {
        // Tight warp (dense regions): cooperative scan of the union.
        for (int z = zlo; z <= zhi; z++) {
            for (int y = ylo; y <= yhi; y++) {
                int rowb = cbase + (z * GD + y) * GD;
                int2 c0 = g_cell[rowb + xlo];
                int2 c1 = g_cell[rowb + xhi];
                int s = c0.x, e = c1.x + c1.y;   // contiguous range (counting sort)
                for (int u = s; u < e; u += 32) {
                    int idx = u + lane;
                    if (idx < e) buf[wloc][lane] = g_pts[pbase + idx];  // coalesced
                    __syncwarp();
                    if (e - u >= 32) {
#pragma unroll
                        for (int i = 0; i < 32; i++) {
                            float4 c = buf[wloc][i];        // LDS broadcast
                            float dx = q.x - c.x, dy = q.y - c.y, dz = q.z - c.z;
                            best = fminf(best, fmaf(dx, dx, fmaf(dy, dy, dz * dz)));
                        }
                    } else {
                        int nn = e - u;
                        for (int i = 0; i < nn; i++) {
                            float4 c = buf[wloc][i];
                            float dx = q.x - c.x, dy = q.y - c.y, dz = q.z - c.z;
                            best = fminf(best, fmaf(dx, dx, fmaf(dy, dy, dz * dz)));
                        }
                    }
                    __syncwarp();
                }
            }
        }
    } else {
        // Loose warp (sparse tails, few candidates): per-lane row scans.
        for (int z = mzlo; z <= mzhi; z++) {
            for (int y = mylo; y <= myhi; y++) {
                int rowb = cbase + (z * GD + y) * GD;
                int2 c0 = g_cell[rowb + mxlo];
                int2 c1 = g_cell[rowb + mxhi];
                int e = c1.x + c1.y;
                for (int u = c0.x; u < e; u++) {
                    float4 tp = g_pts[pbase + u];
                    float dx = q.x - tp.x, dy = q.y - tp.y, dz = q.z - tp.z;
                    best = fminf(best, fmaf(dx, dx, fmaf(dy, dy, dz * dz)));
                }
            }
        }
    }

    // Any point outside a lane's own 3^3 neighborhood is > H away:
    // exact iff best <= H^2.
    if (best <= BOUND2) {
        int orig = __float_as_int(q.w);
        g_mind[d * (Bn * Np) + b * Np + orig] = best;
    } else {
        g_fq[atomicAdd(&g_fcnt, 1)] = t;  // defer to uniform brute-force pass
    }
}

// ---- phase 2: one warp per unresolved query, full coalesced scan ----

__global__ void __launch_bounds__(256)
nn_far() {
    const int lane = threadIdx.x & 31;
    const int wid  = (blockIdx.x * blockDim.x + threadIdx.x) >> 5;  // 2048 warps
    const int nf   = g_fcnt;
    for (int fi = wid; fi < nf; fi += 2048) {
        int t  = g_fq[fi];
        int d  = t >> 15;
        int rr = t & 32767;
        int b  = rr >> 13;
        int k  = rr & 8191;
        float4 q = g_pts[(d * Bn + b) * Np + k];
        const int pbase = ((1 - d) * Bn + b) * Np;

        float best = 3.4e38f;
        for (int i = lane; i < Np; i += 32) {   // coalesced LDG.128 scan
            float4 tp = g_pts[pbase + i];
            float ddx = q.x - tp.x;
            float ddy = q.y - tp.y;
            float ddz = q.z - tp.z;
            float d2 = fmaf(ddx, ddx, fmaf(ddy, ddy, ddz * ddz));
            best = fminf(best, d2);
        }
        // d2 >= 0 in difference form -> raw bits order as uint
        unsigned m = redux_min(__float_as_uint(best));
        if (lane == 0) {
            int orig = __float_as_int(q.w);
            g_mind[d * (Bn * Np) + b * Np + orig] = __uint_as_float(m);
        }
    }
}

// ---- deterministic fixed-order sum ----

__global__ void final_sum(float* out) {
    __shared__ float sh[1024];
    int tid = threadIdx.x;
    float s = 0.0f;
    for (int i = tid; i < NPTS; i += 1024) s += g_mind[i];  // fixed order
    sh[tid] = s;
    __syncthreads();
#pragma unroll
    for (int st = 512; st > 0; st >>= 1) {
        if (tid < st) sh[tid] += sh[tid + st];
        __syncthreads();
    }
    if (tid == 0)
        out[0] = sh[0] / (float)(Bn * Np);  // (sum_fwd + sum_bwd) / (B*G)
}

extern "C" void kernel_launch(void* const* d_in, const int* in_sizes, int n_in,
                              void* d_out, int out_size) {
    const float* src = (const float*)d_in[0];  // (4, 8192, 3) fp32
    const float* tgt = (const float*)d_in[1];  // (4, 8192, 3) fp32
    float* out = (float*)d_out;

    zero_cnt<<<(NSEG * NC) / 1024, 1024>>>();
    count_pts<<<NPTS / 256, 256>>>(src, tgt);
    scan_cells<<<NSEG, 1024>>>();
    scatter_pts<<<NPTS / 256, 256>>>(src, tgt);
    nn_local<<<NPTS / 256, 256>>>();
    nn_far<<<256, 256>>>();
    final_sum<<<1, 1024>>>(out);
}